// round 11
// baseline (speedup 1.0000x reference)
#include <cuda_runtime.h>

#define NB 8
#define NA 65536
#define NG 32

// ---- pass1 config ----
#define AW   64                // anchors per warp
#define WPB  8                 // warps per block
#define ABLK (AW * WPB)        // 512 anchors per block
#define NCH  (NA / ABLK)       // 128 chunks per batch
#define NBLK_A (NCH * NB)      // 1024 blocks

// ---- pass2 config ----
#define TPB 256
#define NCHC (NA / TPB)        // 256 chunks per batch
#define NBLK_C (NCHC * NB)     // 2048 blocks

// Scratch (no allocations allowed)
__device__ float    g_pi[NB * NG * NCH];
__device__ float    g_pu[NB * NG * NCH];
__device__ unsigned g_px[NB * NG * NCH];
__device__ unsigned g_mask[NB * NA];
__device__ float    g_class;
__device__ float    g_coord[NB];
__device__ int      g_cnt[NB];
__device__ int      g_tick;
__device__ int      g_tickA[NB];

// LG = log2(lanes per gt-group); G = 32>>LG anchors per slot-pass. 2 slots.
template <int LG>
__device__ __forceinline__ void kA_impl(
    const float* __restrict__ anchors,   // [A,4] xyxy
    const float* __restrict__ gt,        // [B,G,4] xywh
    int n, int b, int chunk)
{
    constexpr int GSZ = 1 << LG;
    constexpr int G   = 32 >> LG;
    constexpr unsigned MG = (GSZ == 32) ? 0xffffffffu : ((1u << GSZ) - 1u);

    const int tid  = threadIdx.x;
    const int lane = tid & 31, warp = tid >> 5;
    const int gl   = lane & (GSZ - 1);   // this lane's gt
    const int grp  = lane >> LG;         // this lane's anchor slot within pass

    // per-lane gt constants
    float gx1, gy1, gx2, gy2, sg;
    {
        float4 q = ((const float4*)gt)[b * NG + gl];   // cx,cy,w,h
        float hx = q.z * 0.5f, hy = q.w * 0.5f;
        gx1 = q.x - hx; gy1 = q.y - hy;
        gx2 = q.x + hx; gy2 = q.y + hy;
        sg  = (gx2 - gx1) * (gy2 - gy1);
        if (gl >= n) {          // sentinel: zero overlap with any anchor
            gx1 = 3e9f; gx2 = 3e9f; gy1 = 0.f; gy2 = 1.f; sg = 0.f;
        }
    }

    const int wbase = chunk * ABLK + warp * AW;
    unsigned* __restrict__ mrow = &g_mask[b * NA];

    // 2 independent argmax accumulators — overlapping select chains
    float    bi0 = 0.f, bu0 = 1.f, bi1 = 0.f, bu1 = 1.f;
    unsigned bx0 = (unsigned)(wbase + grp);
    unsigned bx1 = (unsigned)(wbase + G + grp);

#pragma unroll
    for (int it = 0; it < AW / (2 * G); it++) {
        const int a = wbase + it * 2 * G;
        unsigned bal0, bal1;
#pragma unroll
        for (int k = 0; k < 2; k++) {
            const int ak = a + k * G + grp;
            float4 q = __ldg(((const float4*)anchors) + ak);
            float sa = (q.z - q.x) * (q.w - q.y);
            float lx = fmaxf(q.x, gx1), ly = fmaxf(q.y, gy1);
            float rx = fminf(q.z, gx2), ry = fminf(q.w, gy2);
            float w  = fmaxf(rx - lx, 0.f), h = fmaxf(ry - ly, 0.f);
            float inter = w * h;
            float u = (sa + sg) - inter;
            // exact sign of inter - 0.5u (single rounding; 0.5u exact)
            unsigned bal = __ballot_sync(0xffffffffu, fmaf(-0.5f, u, inter) > 0.f);
            // iou > best  <=>  inter*bu > bi*u  (u,bu > 0); strict > keeps
            // earliest anchor in this slot's ascending sequence
            if (k == 0) {
                bal0 = bal;
                bool better = inter * bu0 > bi0 * u;
                bi0 = better ? inter : bi0;
                bu0 = better ? u     : bu0;
                bx0 = better ? (unsigned)ak : bx0;
            } else {
                bal1 = bal;
                bool better = inter * bu1 > bi1 * u;
                bi1 = better ? inter : bi1;
                bu1 = better ? u     : bu1;
                bx1 = better ? (unsigned)ak : bx1;
            }
        }
        if (G == 1) {
            if (lane == 0)
                *(uint2*)&mrow[a] = make_uint2(bal0, bal1);
        } else {
            if (gl == 0) {      // one lane per group stores its gsz-bit field
                mrow[a + grp]     = (bal0 >> lane) & MG;
                mrow[a + G + grp] = (bal1 >> lane) & MG;
            }
        }
    }

    // merge 2 slots (disjoint anchor sets; explicit index tie-break)
    float Bi = bi0, Bu = bu0; unsigned Bx = bx0;
    {
        float A = bi1 * Bu, C = Bi * bu1;
        if (A > C || (A == C && bx1 < Bx)) { Bi = bi1; Bu = bu1; Bx = bx1; }
    }

    __shared__ float    s_bi[WPB][32], s_bu[WPB][32];
    __shared__ unsigned s_bx[WPB][32];
    s_bi[warp][lane] = Bi; s_bu[warp][lane] = Bu; s_bx[warp][lane] = Bx;
    __syncthreads();

    if (tid < GSZ) {                // one thread per g: merge warps x groups
        float Ri = 0.f, Ru = 1.f; unsigned Rx = 0xffffffffu;
#pragma unroll
        for (int w = 0; w < WPB; w++)
#pragma unroll
            for (int j = 0; j < G; j++) {
                const int l = tid + (j << LG);
                float oi = s_bi[w][l], ou = s_bu[w][l];
                unsigned ox = s_bx[w][l];
                float A = oi * Ru, C = Ri * ou;
                if (A > C || (A == C && ox < Rx)) { Ri = oi; Ru = ou; Rx = ox; }
            }
        const int p = (b * NG + tid) * NCH + chunk;
        g_pi[p] = Ri; g_pu[p] = Ru; g_px[p] = Rx;
    }

    // per-batch ticket: last block of this batch finalizes (fused kB)
    __shared__ bool s_last;
    __syncthreads();
    if (tid == 0) {
        __threadfence();
        s_last = (atomicAdd(&g_tickA[b], 1) == NCH - 1);
    }
    __syncthreads();
    if (!s_last) return;

    {
        const int g = tid >> 3, s = tid & 7;     // 8 threads per g
        const int base = (b * NG + g) * NCH;
        float Fi = 0.f, Fu = 1.f; unsigned Fx = 0xffffffffu;
#pragma unroll 4
        for (int c = s * (NCH / 8); c < (s + 1) * (NCH / 8); c++) {
            float oi = __ldcg(&g_pi[base + c]);
            float ou = __ldcg(&g_pu[base + c]);
            unsigned ox = __ldcg(&g_px[base + c]);
            float A = oi * Fu, C = Fi * ou;
            if (A > C || (A == C && ox < Fx)) { Fi = oi; Fu = ou; Fx = ox; }
        }
#pragma unroll
        for (int off = 4; off; off >>= 1) {
            float    oi = __shfl_down_sync(0xffffffffu, Fi, off, 8);
            float    ou = __shfl_down_sync(0xffffffffu, Fu, off, 8);
            unsigned ox = __shfl_down_sync(0xffffffffu, Fx, off, 8);
            float A = oi * Fu, C = Fi * ou;
            if (A > C || (A == C && ox < Fx)) { Fi = oi; Fu = ou; Fx = ox; }
        }
        if (s == 0 && g < n)
            atomicOr(&g_mask[b * NA + Fx], 1u << g);
        if (tid == 0) {
            g_coord[b] = 0.f; g_cnt[b] = 0; g_tickA[b] = 0;
            if (b == 0) { g_class = 0.f; g_tick = 0; }
        }
    }
}

__global__ __launch_bounds__(256) void kA(
    const float* __restrict__ anchors, const float* __restrict__ gt,
    const int* __restrict__ nobj)
{
    const int b = blockIdx.x & (NB - 1), chunk = blockIdx.x >> 3;
    const int n = __ldg(nobj + b);
    if (n <= 16)
        kA_impl<4>(anchors, gt, n, b, chunk);
    else
        kA_impl<5>(anchors, gt, n, b, chunk);
}

// -------- Pass 2: class + coord losses, ticketed finalize --------
__global__ __launch_bounds__(TPB) void kC(
    const float* __restrict__ boxes,   // [B,A,4]
    const float* __restrict__ cls,     // [B,A,2]
    const float* __restrict__ gt,      // [B,G,4]
    float* __restrict__ out)
{
    const int b    = blockIdx.y;
    const int tid  = threadIdx.x;
    const int lane = tid & 31, warp = tid >> 5;
    const int a    = blockIdx.x * TPB + tid;     // one anchor per thread

    __shared__ float s_g[4][NG];
    if (tid < NG) {
        float4 q = ((const float4*)gt)[b * NG + tid];
        float hx = q.z * 0.5f, hy = q.w * 0.5f;
        s_g[0][tid] = q.x - hx; s_g[1][tid] = q.y - hy;
        s_g[2][tid] = q.x + hx; s_g[3][tid] = q.y + hy;
    }
    __syncthreads();

    unsigned m = g_mask[b * NA + a];
    float2 c  = ((const float2*)cls)[b * NA + a];

    float p  = m ? c.y : c.x;
    float om = 1.f - p;
    float cls_sum = om * om * (-__logf(p));

    float crd_sum = 0.f; int cnt = 0;
    if (m) {
        float4 q = ((const float4*)boxes)[b * NA + a];
        do {
            int g = __ffs(m) - 1; m &= m - 1;
            crd_sum += fabsf(q.x - s_g[0][g]) + fabsf(q.y - s_g[1][g])
                     + fabsf(q.z - s_g[2][g]) + fabsf(q.w - s_g[3][g]);
            cnt++;
        } while (m);
    }

#pragma unroll
    for (int off = 16; off; off >>= 1) {
        cls_sum += __shfl_down_sync(0xffffffffu, cls_sum, off);
        crd_sum += __shfl_down_sync(0xffffffffu, crd_sum, off);
        cnt     += __shfl_down_sync(0xffffffffu, cnt, off);
    }
    __shared__ float r_cls[8], r_crd[8];
    __shared__ int   r_cnt[8];
    if (lane == 0) { r_cls[warp] = cls_sum; r_crd[warp] = crd_sum; r_cnt[warp] = cnt; }
    __syncthreads();
    if (tid == 0) {
        float tc = 0.f, tr = 0.f; int tn = 0;
#pragma unroll
        for (int w = 0; w < 8; w++) { tc += r_cls[w]; tr += r_crd[w]; tn += r_cnt[w]; }
        atomicAdd(&g_class, tc);
        atomicAdd(&g_coord[b], tr);
        atomicAdd(&g_cnt[b], tn);
        __threadfence();
        if (atomicAdd(&g_tick, 1) == NBLK_C - 1) {   // last block finalizes
            __threadfence();
            float coord = 0.f;
#pragma unroll
            for (int bb = 0; bb < NB; bb++) {
                float cc = *(volatile float*)&g_coord[bb];
                int   nn = *(volatile int*)&g_cnt[bb];
                coord += cc / (4.f * (float)nn);
            }
            float cl = (*(volatile float*)&g_class) * (0.01f / 8.f);
            float co = coord * (1.0f / 8.f);
            out[0] = cl + co;
            out[1] = cl;
            out[2] = co;
        }
    }
}

extern "C" void kernel_launch(void* const* d_in, const int* in_sizes, int n_in,
                              void* d_out, int out_size) {
    const float* boxes   = (const float*)d_in[0];   // [8,65536,4]
    const float* classes = (const float*)d_in[1];   // [8,65536,2]
    const float* anchors = (const float*)d_in[2];   // [65536,4]
    const float* gt      = (const float*)d_in[3];   // [8,32,4]
    const int*   nobj    = (const int*)d_in[4];     // [8]
    float* out = (float*)d_out;

    kA<<<NBLK_A, 256>>>(anchors, gt, nobj);
    kC<<<dim3(NCHC, NB), TPB>>>(boxes, classes, gt, out);
}

// round 12
// speedup vs baseline: 1.0919x; 1.0919x over previous
#include <cuda_runtime.h>

#define NB 8
#define NA 65536
#define NG 32

#define AW   64                // anchors per warp
#define WPB  8                 // warps per block
#define ABLK (AW * WPB)        // 512 anchors per block
#define NCH  (NA / ABLK)       // 128 chunks per batch
#define NBLK (NCH * NB)        // 1024 blocks

// Scratch (no allocations allowed)
__device__ float    g_pi[NB * NG * NCH];
__device__ float    g_pu[NB * NG * NCH];
__device__ unsigned g_px[NB * NG * NCH];
__device__ float    g_class;
__device__ float    g_coord[NB];
__device__ float    g_cntf[NB];
__device__ int      g_tickA[NB];
__device__ int      g_tickF;

// LG = log2(lanes per gt-group); G = 32>>LG anchors per slot-pass, 2 slots.
template <int LG>
__device__ __forceinline__ void kern_impl(
    const float* __restrict__ boxes,     // [B,A,4]
    const float* __restrict__ cls,       // [B,A,2]
    const float* __restrict__ anchors,   // [A,4] xyxy
    const float* __restrict__ gt,        // [B,G,4] xywh
    float* __restrict__ out,
    int n, int b, int chunk)
{
    constexpr int GSZ = 1 << LG;
    constexpr int G   = 32 >> LG;
    constexpr unsigned MG = (GSZ == 32) ? 0xffffffffu : ((1u << GSZ) - 1u);

    const int tid  = threadIdx.x;
    const int lane = tid & 31, warp = tid >> 5;
    const int gl   = lane & (GSZ - 1);
    const int grp  = lane >> LG;

    __shared__ float    s_gx1[NG], s_gy1[NG], s_gx2[NG], s_gy2[NG], s_sg[NG];
    __shared__ unsigned s_bal[WPB][AW];          // [AW/G] used
    __shared__ float    s_bi[WPB][32], s_bu[WPB][32];
    __shared__ unsigned s_bx[WPB][32];
    __shared__ float    r_cls[WPB], r_crd[WPB], r_cnt[WPB];
    __shared__ unsigned sFx[NG];
    __shared__ bool     s_last;

    // ---- preamble: gt xyxy + area into smem (for coord & finalize) ----
    if (tid < NG) {
        float4 q = ((const float4*)gt)[b * NG + tid];
        float hx = q.z * 0.5f, hy = q.w * 0.5f;
        float x1 = q.x - hx, y1 = q.y - hy, x2 = q.x + hx, y2 = q.y + hy;
        s_gx1[tid] = x1; s_gy1[tid] = y1; s_gx2[tid] = x2; s_gy2[tid] = y2;
        s_sg[tid]  = (x2 - x1) * (y2 - y1);
    }
    // per-lane gt regs (sentinel for invalid g)
    float gx1, gy1, gx2, gy2, sg;
    {
        float4 q = ((const float4*)gt)[b * NG + gl];
        float hx = q.z * 0.5f, hy = q.w * 0.5f;
        gx1 = q.x - hx; gy1 = q.y - hy; gx2 = q.x + hx; gy2 = q.y + hy;
        sg  = (gx2 - gx1) * (gy2 - gy1);
        if (gl >= n) { gx1 = 3e9f; gx2 = 3e9f; gy1 = 0.f; gy2 = 1.f; sg = 0.f; }
    }
    __syncthreads();

    const int wbase = chunk * ABLK + warp * AW;

    // ---- phase 1: IoU ballots + 2-slot argmax ----
    float    bi0 = 0.f, bu0 = 1.f, bi1 = 0.f, bu1 = 1.f;
    unsigned bx0 = (unsigned)(wbase + grp), bx1 = (unsigned)(wbase + G + grp);

#pragma unroll
    for (int it = 0; it < AW / (2 * G); it++) {
        const int a = wbase + it * 2 * G;
        unsigned bal0, bal1;
        {
            const int ak = a + grp;
            float4 q = __ldg(((const float4*)anchors) + ak);
            float sa = (q.z - q.x) * (q.w - q.y);
            float lx = fmaxf(q.x, gx1), ly = fmaxf(q.y, gy1);
            float rx = fminf(q.z, gx2), ry = fminf(q.w, gy2);
            float w = fmaxf(rx - lx, 0.f), h = fmaxf(ry - ly, 0.f);
            float inter = w * h, u = (sa + sg) - inter;
            bal0 = __ballot_sync(0xffffffffu, fmaf(-0.5f, u, inter) > 0.f);
            bool bet = inter * bu0 > bi0 * u;
            bi0 = bet ? inter : bi0; bu0 = bet ? u : bu0;
            bx0 = bet ? (unsigned)ak : bx0;
        }
        {
            const int ak = a + G + grp;
            float4 q = __ldg(((const float4*)anchors) + ak);
            float sa = (q.z - q.x) * (q.w - q.y);
            float lx = fmaxf(q.x, gx1), ly = fmaxf(q.y, gy1);
            float rx = fminf(q.z, gx2), ry = fminf(q.w, gy2);
            float w = fmaxf(rx - lx, 0.f), h = fmaxf(ry - ly, 0.f);
            float inter = w * h, u = (sa + sg) - inter;
            bal1 = __ballot_sync(0xffffffffu, fmaf(-0.5f, u, inter) > 0.f);
            bool bet = inter * bu1 > bi1 * u;
            bi1 = bet ? inter : bi1; bu1 = bet ? u : bu1;
            bx1 = bet ? (unsigned)ak : bx1;
        }
        if (lane == 0) {
            s_bal[warp][it * 2]     = bal0;
            s_bal[warp][it * 2 + 1] = bal1;
        }
    }
    __syncwarp();

    // ---- phase 2: class + coord over this warp's 64 anchors (2/lane) ----
    float cls_sum = 0.f, crd_sum = 0.f, cnt_sum = 0.f;
    {
        float4 c4 = __ldg((const float4*)cls + ((b * NA + wbase) >> 1) + lane);
#pragma unroll
        for (int j = 0; j < 2; j++) {
            const int o  = 2 * lane + j;
            const int it = o / (2 * G);
            const int k  = (o / G) & 1;
            const int g2 = o & (G - 1);
            unsigned word = (s_bal[warp][it * 2 + k] >> (g2 * GSZ)) & MG;
            float pc0 = j ? c4.z : c4.x, pc1 = j ? c4.w : c4.y;
            float p = word ? pc1 : pc0;
            float om = 1.f - p;
            cls_sum += om * om * (-__logf(p));
            if (word) {
                float4 qb = __ldg((const float4*)boxes + b * NA + wbase + o);
                do {
                    int g = __ffs(word) - 1; word &= word - 1;
                    crd_sum += fabsf(qb.x - s_gx1[g]) + fabsf(qb.y - s_gy1[g])
                             + fabsf(qb.z - s_gx2[g]) + fabsf(qb.w - s_gy2[g]);
                    cnt_sum += 1.f;
                } while (word);
            }
        }
    }
#pragma unroll
    for (int off = 16; off; off >>= 1) {
        cls_sum += __shfl_down_sync(0xffffffffu, cls_sum, off);
        crd_sum += __shfl_down_sync(0xffffffffu, crd_sum, off);
        cnt_sum += __shfl_down_sync(0xffffffffu, cnt_sum, off);
    }
    if (lane == 0) { r_cls[warp] = cls_sum; r_crd[warp] = crd_sum; r_cnt[warp] = cnt_sum; }

    // argmax slot merge + deposit
    float Bi = bi0, Bu = bu0; unsigned Bx = bx0;
    {
        float A = bi1 * Bu, C = Bi * bu1;
        if (A > C || (A == C && bx1 < Bx)) { Bi = bi1; Bu = bu1; Bx = bx1; }
    }
    s_bi[warp][lane] = Bi; s_bu[warp][lane] = Bu; s_bx[warp][lane] = Bx;
    __syncthreads();

    if (tid < GSZ) {                // one thread per g: merge warps x groups
        float Ri = 0.f, Ru = 1.f; unsigned Rx = 0xffffffffu;
#pragma unroll
        for (int w = 0; w < WPB; w++)
#pragma unroll
            for (int j = 0; j < G; j++) {
                const int l = tid + (j << LG);
                float oi = s_bi[w][l], ou = s_bu[w][l];
                unsigned ox = s_bx[w][l];
                float A = oi * Ru, C = Ri * ou;
                if (A > C || (A == C && ox < Rx)) { Ri = oi; Ru = ou; Rx = ox; }
            }
        const int p = (b * NG + tid) * NCH + chunk;
        g_pi[p] = Ri; g_pu[p] = Ru; g_px[p] = Rx;
    }
    if (tid == 0) {
        float tc = 0.f, tr = 0.f, tn = 0.f;
#pragma unroll
        for (int w = 0; w < WPB; w++) { tc += r_cls[w]; tr += r_crd[w]; tn += r_cnt[w]; }
        atomicAdd(&g_class, tc);
        atomicAdd(&g_coord[b], tr);
        atomicAdd(&g_cntf[b], tn);
    }
    __syncthreads();                // all g_pi stores + atomics done block-wide

    if (tid == 0) {
        __threadfence();
        s_last = (atomicAdd(&g_tickA[b], 1) == NCH - 1);
    }
    __syncthreads();
    if (!s_last) return;

    // ---- per-batch finalize: argmax over chunks, forced corrections ----
    {
        const int g = tid >> 3, s = tid & 7;
        const int base = (b * NG + g) * NCH;
        float Fi = 0.f, Fu = 1.f; unsigned Fx = 0xffffffffu;
#pragma unroll 4
        for (int c = s * (NCH / 8); c < (s + 1) * (NCH / 8); c++) {
            float oi = __ldcg(&g_pi[base + c]);
            float ou = __ldcg(&g_pu[base + c]);
            unsigned ox = __ldcg(&g_px[base + c]);
            float A = oi * Fu, C = Fi * ou;
            if (A > C || (A == C && ox < Fx)) { Fi = oi; Fu = ou; Fx = ox; }
        }
#pragma unroll
        for (int off = 4; off; off >>= 1) {
            float    oi = __shfl_down_sync(0xffffffffu, Fi, off, 8);
            float    ou = __shfl_down_sync(0xffffffffu, Fu, off, 8);
            unsigned ox = __shfl_down_sync(0xffffffffu, Fx, off, 8);
            float A = oi * Fu, C = Fi * ou;
            if (A > C || (A == C && ox < Fx)) { Fi = oi; Fu = ou; Fx = ox; }
        }
        if (s == 0) sFx[g] = Fx;
    }
    __syncthreads();

    float clsc = 0.f, crdc = 0.f, cntc = 0.f;
    if (tid < n) {                  // thread per valid g
        unsigned fx = sFx[tid];
        float4 qa = __ldg((const float4*)anchors + fx);
        float sa = (qa.z - qa.x) * (qa.w - qa.y);
        unsigned word = 0;
        for (int g2 = 0; g2 < n; g2++) {   // recompute this anchor's iou-mask
            float lx = fmaxf(qa.x, s_gx1[g2]), ly = fmaxf(qa.y, s_gy1[g2]);
            float rx = fminf(qa.z, s_gx2[g2]), ry = fminf(qa.w, s_gy2[g2]);
            float w = fmaxf(rx - lx, 0.f), h = fmaxf(ry - ly, 0.f);
            float inter = w * h, u = (sa + s_sg[g2]) - inter;
            if (fmaf(-0.5f, u, inter) > 0.f) word |= 1u << g2;
        }
        if (!((word >> tid) & 1)) { // forced pair not already counted
            float4 qb = __ldg((const float4*)boxes + b * NA + fx);
            crdc = fabsf(qb.x - s_gx1[tid]) + fabsf(qb.y - s_gy1[tid])
                 + fabsf(qb.z - s_gx2[tid]) + fabsf(qb.w - s_gy2[tid]);
            cntc = 1.f;
        }
        if (word == 0) {            // anchor counted as negative in phase 2
            bool first = true;      // dedupe: smallest g forcing this anchor
            for (int g2 = 0; g2 < tid; g2++) if (sFx[g2] == fx) first = false;
            if (first) {
                float2 cc = __ldg((const float2*)cls + b * NA + fx);
                float o1 = 1.f - cc.y, o0 = 1.f - cc.x;
                clsc = o1 * o1 * (-__logf(cc.y)) - o0 * o0 * (-__logf(cc.x));
            }
        }
    }
    if (tid < 32) {
#pragma unroll
        for (int off = 16; off; off >>= 1) {
            clsc += __shfl_down_sync(0xffffffffu, clsc, off);
            crdc += __shfl_down_sync(0xffffffffu, crdc, off);
            cntc += __shfl_down_sync(0xffffffffu, cntc, off);
        }
    }
    if (tid == 0) {
        atomicAdd(&g_class, clsc);
        atomicAdd(&g_coord[b], crdc);
        atomicAdd(&g_cntf[b], cntc);
        g_tickA[b] = 0;
        __threadfence();
        if (atomicAdd(&g_tickF, 1) == NB - 1) {      // last batch: emit output
            __threadfence();
            float coord = 0.f;
#pragma unroll
            for (int bb = 0; bb < NB; bb++)
                coord += (*(volatile float*)&g_coord[bb])
                       / (4.f * (*(volatile float*)&g_cntf[bb]));
            float cl = (*(volatile float*)&g_class) * (0.01f / 8.f);
            float co = coord * (1.0f / 8.f);
            out[0] = cl + co; out[1] = cl; out[2] = co;
            // reset for next graph replay
            g_class = 0.f; g_tickF = 0;
#pragma unroll
            for (int bb = 0; bb < NB; bb++) { g_coord[bb] = 0.f; g_cntf[bb] = 0.f; }
        }
    }
}

__global__ __launch_bounds__(256) void kFused(
    const float* __restrict__ boxes, const float* __restrict__ cls,
    const float* __restrict__ anchors, const float* __restrict__ gt,
    const int* __restrict__ nobj, float* __restrict__ out)
{
    const int b = blockIdx.x & (NB - 1), chunk = blockIdx.x >> 3;
    const int n = __ldg(nobj + b);
    if (n <= 16)
        kern_impl<4>(boxes, cls, anchors, gt, out, n, b, chunk);
    else
        kern_impl<5>(boxes, cls, anchors, gt, out, n, b, chunk);
}

extern "C" void kernel_launch(void* const* d_in, const int* in_sizes, int n_in,
                              void* d_out, int out_size) {
    const float* boxes   = (const float*)d_in[0];   // [8,65536,4]
    const float* classes = (const float*)d_in[1];   // [8,65536,2]
    const float* anchors = (const float*)d_in[2];   // [65536,4]
    const float* gt      = (const float*)d_in[3];   // [8,32,4]
    const int*   nobj    = (const int*)d_in[4];     // [8]
    float* out = (float*)d_out;

    kFused<<<NBLK, 256>>>(boxes, classes, anchors, gt, nobj, out);
}

// round 13
// speedup vs baseline: 1.1308x; 1.0356x over previous
#include <cuda_runtime.h>

#define NB 8
#define NA 65536
#define NG 32

#define AW   64                // anchors per warp
#define WPB  8                 // warps per block
#define ABLK (AW * WPB)        // 512 anchors per block
#define NCH  (NA / ABLK)       // 128 chunks per batch
#define NBLK (NCH * NB)        // 1024 blocks

// Scratch (no allocations allowed)
__device__ float    g_pi[NB * NG * NCH];
__device__ float    g_pu[NB * NG * NCH];
__device__ unsigned g_px[NB * NG * NCH];
__device__ float    g_class;
__device__ float    g_coord[NB];
__device__ float    g_cntf[NB];
__device__ int      g_tickA[NB];
__device__ int      g_tickF;

// LG = log2(lanes per gt-group); G = 32>>LG anchors per slot, 4 slots/pass.
template <int LG>
__device__ __forceinline__ void kern_impl(
    const float* __restrict__ boxes,     // [B,A,4]
    const float* __restrict__ cls,       // [B,A,2]
    const float* __restrict__ anchors,   // [A,4] xyxy
    const float* __restrict__ gt,        // [B,G,4] xywh
    float* __restrict__ out,
    int n, int b, int chunk)
{
    constexpr int GSZ = 1 << LG;
    constexpr int G   = 32 >> LG;
    constexpr unsigned MG = (GSZ == 32) ? 0xffffffffu : ((1u << GSZ) - 1u);

    const int tid  = threadIdx.x;
    const int lane = tid & 31, warp = tid >> 5;
    const int gl   = lane & (GSZ - 1);
    const int grp  = lane >> LG;

    __shared__ float    s_gx1[NG], s_gy1[NG], s_gx2[NG], s_gy2[NG], s_sg[NG];
    __shared__ unsigned s_bal[WPB][AW];          // [AW/G] used
    __shared__ float    s_bi[WPB][32], s_bu[WPB][32];
    __shared__ unsigned s_bx[WPB][32];
    __shared__ float    r_cls[WPB], r_crd[WPB], r_cnt[WPB];
    __shared__ unsigned sFx[NG];
    __shared__ bool     s_last;

    // ---- preamble ----
    if (tid < NG) {
        float4 q = ((const float4*)gt)[b * NG + tid];
        float hx = q.z * 0.5f, hy = q.w * 0.5f;
        float x1 = q.x - hx, y1 = q.y - hy, x2 = q.x + hx, y2 = q.y + hy;
        s_gx1[tid] = x1; s_gy1[tid] = y1; s_gx2[tid] = x2; s_gy2[tid] = y2;
        s_sg[tid]  = (x2 - x1) * (y2 - y1);
    }
    float gx1, gy1, gx2, gy2, sg;
    {
        float4 q = ((const float4*)gt)[b * NG + gl];
        float hx = q.z * 0.5f, hy = q.w * 0.5f;
        gx1 = q.x - hx; gy1 = q.y - hy; gx2 = q.x + hx; gy2 = q.y + hy;
        sg  = (gx2 - gx1) * (gy2 - gy1);
        if (gl >= n) { gx1 = 3e9f; gx2 = 3e9f; gy1 = 0.f; gy2 = 1.f; sg = 0.f; }
    }
    __syncthreads();

    const int wbase = chunk * ABLK + warp * AW;

    // prefetch phase-2 cls data (independent of phase 1; hides DRAM latency)
    float4 c4 = __ldg((const float4*)cls + ((b * NA + wbase) >> 1) + lane);

    // ---- phase 1: IoU ballots + 4-slot argmax ----
    float    bi[4], bu[4];
    unsigned bx[4];
#pragma unroll
    for (int k = 0; k < 4; k++) {
        bi[k] = 0.f; bu[k] = 1.f; bx[k] = (unsigned)(wbase + k * G + grp);
    }

#pragma unroll
    for (int it = 0; it < AW / (4 * G); it++) {
        const int a = wbase + it * 4 * G;
        unsigned bals[4];
#pragma unroll
        for (int k = 0; k < 4; k++) {
            const int ak = a + k * G + grp;
            float4 q = __ldg(((const float4*)anchors) + ak);
            float sa = (q.z - q.x) * (q.w - q.y);
            float lx = fmaxf(q.x, gx1), ly = fmaxf(q.y, gy1);
            float rx = fminf(q.z, gx2), ry = fminf(q.w, gy2);
            float w = fmaxf(rx - lx, 0.f), h = fmaxf(ry - ly, 0.f);
            float inter = w * h, u = (sa + sg) - inter;
            // exact sign of inter - 0.5u (single rounding; 0.5u exact)
            bals[k] = __ballot_sync(0xffffffffu, fmaf(-0.5f, u, inter) > 0.f);
            // iou > best  <=>  inter*bu > bi*u  (u,bu > 0); strict > keeps
            // earliest anchor in this slot's ascending sequence
            bool bet = inter * bu[k] > bi[k] * u;
            bi[k] = bet ? inter : bi[k];
            bu[k] = bet ? u     : bu[k];
            bx[k] = bet ? (unsigned)ak : bx[k];
        }
        if (lane == 0) {
#pragma unroll
            for (int k = 0; k < 4; k++) s_bal[warp][it * 4 + k] = bals[k];
        }
    }
    __syncwarp();

    // ---- phase 2: class + coord over this warp's 64 anchors (2/lane) ----
    float cls_sum = 0.f, crd_sum = 0.f, cnt_sum = 0.f;
    {
#pragma unroll
        for (int j = 0; j < 2; j++) {
            const int o  = 2 * lane + j;
            unsigned word = (s_bal[warp][o / G] >> ((o & (G - 1)) * GSZ)) & MG;
            float pc0 = j ? c4.z : c4.x, pc1 = j ? c4.w : c4.y;
            float p = word ? pc1 : pc0;
            float om = 1.f - p;
            cls_sum += om * om * (-__logf(p));
            if (word) {
                float4 qb = __ldg((const float4*)boxes + b * NA + wbase + o);
                do {
                    int g = __ffs(word) - 1; word &= word - 1;
                    crd_sum += fabsf(qb.x - s_gx1[g]) + fabsf(qb.y - s_gy1[g])
                             + fabsf(qb.z - s_gx2[g]) + fabsf(qb.w - s_gy2[g]);
                    cnt_sum += 1.f;
                } while (word);
            }
        }
    }
#pragma unroll
    for (int off = 16; off; off >>= 1) {
        cls_sum += __shfl_down_sync(0xffffffffu, cls_sum, off);
        crd_sum += __shfl_down_sync(0xffffffffu, crd_sum, off);
        cnt_sum += __shfl_down_sync(0xffffffffu, cnt_sum, off);
    }
    if (lane == 0) { r_cls[warp] = cls_sum; r_crd[warp] = crd_sum; r_cnt[warp] = cnt_sum; }

    // argmax slot merge + deposit
    float Bi = bi[0], Bu = bu[0]; unsigned Bx = bx[0];
#pragma unroll
    for (int k = 1; k < 4; k++) {
        float A = bi[k] * Bu, C = Bi * bu[k];
        if (A > C || (A == C && bx[k] < Bx)) { Bi = bi[k]; Bu = bu[k]; Bx = bx[k]; }
    }
    s_bi[warp][lane] = Bi; s_bu[warp][lane] = Bu; s_bx[warp][lane] = Bx;
    __syncthreads();

    if (tid < GSZ) {                // one thread per g: merge warps x groups
        float Ri = 0.f, Ru = 1.f; unsigned Rx = 0xffffffffu;
#pragma unroll
        for (int w = 0; w < WPB; w++)
#pragma unroll
            for (int j = 0; j < G; j++) {
                const int l = tid + (j << LG);
                float oi = s_bi[w][l], ou = s_bu[w][l];
                unsigned ox = s_bx[w][l];
                float A = oi * Ru, C = Ri * ou;
                if (A > C || (A == C && ox < Rx)) { Ri = oi; Ru = ou; Rx = ox; }
            }
        const int p = (b * NG + tid) * NCH + chunk;
        g_pi[p] = Ri; g_pu[p] = Ru; g_px[p] = Rx;
    }
    if (tid == 0) {
        float tc = 0.f, tr = 0.f, tn = 0.f;
#pragma unroll
        for (int w = 0; w < WPB; w++) { tc += r_cls[w]; tr += r_crd[w]; tn += r_cnt[w]; }
        atomicAdd(&g_class, tc);
        atomicAdd(&g_coord[b], tr);
        atomicAdd(&g_cntf[b], tn);
    }
    __syncthreads();                // all g_pi stores + atomics done block-wide

    if (tid == 0) {
        __threadfence();
        s_last = (atomicAdd(&g_tickA[b], 1) == NCH - 1);
    }
    __syncthreads();
    if (!s_last) return;

    // ---- per-batch finalize: argmax over chunks, forced corrections ----
    {
        const int g = tid >> 3, s = tid & 7;
        const int base = (b * NG + g) * NCH;
        float Fi = 0.f, Fu = 1.f; unsigned Fx = 0xffffffffu;
#pragma unroll 4
        for (int c = s * (NCH / 8); c < (s + 1) * (NCH / 8); c++) {
            float oi = __ldcg(&g_pi[base + c]);
            float ou = __ldcg(&g_pu[base + c]);
            unsigned ox = __ldcg(&g_px[base + c]);
            float A = oi * Fu, C = Fi * ou;
            if (A > C || (A == C && ox < Fx)) { Fi = oi; Fu = ou; Fx = ox; }
        }
#pragma unroll
        for (int off = 4; off; off >>= 1) {
            float    oi = __shfl_down_sync(0xffffffffu, Fi, off, 8);
            float    ou = __shfl_down_sync(0xffffffffu, Fu, off, 8);
            unsigned ox = __shfl_down_sync(0xffffffffu, Fx, off, 8);
            float A = oi * Fu, C = Fi * ou;
            if (A > C || (A == C && ox < Fx)) { Fi = oi; Fu = ou; Fx = ox; }
        }
        if (s == 0) sFx[g] = Fx;
    }
    __syncthreads();

    float clsc = 0.f, crdc = 0.f, cntc = 0.f;
    if (tid < n) {                  // thread per valid g
        unsigned fx = sFx[tid];
        float4 qa = __ldg((const float4*)anchors + fx);
        float sa = (qa.z - qa.x) * (qa.w - qa.y);
        unsigned word = 0;
        for (int g2 = 0; g2 < n; g2++) {   // recompute this anchor's iou-mask
            float lx = fmaxf(qa.x, s_gx1[g2]), ly = fmaxf(qa.y, s_gy1[g2]);
            float rx = fminf(qa.z, s_gx2[g2]), ry = fminf(qa.w, s_gy2[g2]);
            float w = fmaxf(rx - lx, 0.f), h = fmaxf(ry - ly, 0.f);
            float inter = w * h, u = (sa + s_sg[g2]) - inter;
            if (fmaf(-0.5f, u, inter) > 0.f) word |= 1u << g2;
        }
        if (!((word >> tid) & 1)) { // forced pair not already counted
            float4 qb = __ldg((const float4*)boxes + b * NA + fx);
            crdc = fabsf(qb.x - s_gx1[tid]) + fabsf(qb.y - s_gy1[tid])
                 + fabsf(qb.z - s_gx2[tid]) + fabsf(qb.w - s_gy2[tid]);
            cntc = 1.f;
        }
        if (word == 0) {            // anchor counted as negative in phase 2
            bool first = true;      // dedupe: smallest g forcing this anchor
            for (int g2 = 0; g2 < tid; g2++) if (sFx[g2] == fx) first = false;
            if (first) {
                float2 cc = __ldg((const float2*)cls + b * NA + fx);
                float o1 = 1.f - cc.y, o0 = 1.f - cc.x;
                clsc = o1 * o1 * (-__logf(cc.y)) - o0 * o0 * (-__logf(cc.x));
            }
        }
    }
    if (tid < 32) {
#pragma unroll
        for (int off = 16; off; off >>= 1) {
            clsc += __shfl_down_sync(0xffffffffu, clsc, off);
            crdc += __shfl_down_sync(0xffffffffu, crdc, off);
            cntc += __shfl_down_sync(0xffffffffu, cntc, off);
        }
    }
    if (tid == 0) {
        atomicAdd(&g_class, clsc);
        atomicAdd(&g_coord[b], crdc);
        atomicAdd(&g_cntf[b], cntc);
        g_tickA[b] = 0;
        __threadfence();
        if (atomicAdd(&g_tickF, 1) == NB - 1) {      // last batch: emit output
            __threadfence();
            float coord = 0.f;
#pragma unroll
            for (int bb = 0; bb < NB; bb++)
                coord += (*(volatile float*)&g_coord[bb])
                       / (4.f * (*(volatile float*)&g_cntf[bb]));
            float cl = (*(volatile float*)&g_class) * (0.01f / 8.f);
            float co = coord * (1.0f / 8.f);
            out[0] = cl + co; out[1] = cl; out[2] = co;
            // reset for next graph replay
            g_class = 0.f; g_tickF = 0;
#pragma unroll
            for (int bb = 0; bb < NB; bb++) { g_coord[bb] = 0.f; g_cntf[bb] = 0.f; }
        }
    }
}

__global__ __launch_bounds__(256) void kFused(
    const float* __restrict__ boxes, const float* __restrict__ cls,
    const float* __restrict__ anchors, const float* __restrict__ gt,
    const int* __restrict__ nobj, float* __restrict__ out)
{
    const int b = blockIdx.x & (NB - 1), chunk = blockIdx.x >> 3;
    const int n = __ldg(nobj + b);
    if (n <= 16)
        kern_impl<4>(boxes, cls, anchors, gt, out, n, b, chunk);
    else
        kern_impl<5>(boxes, cls, anchors, gt, out, n, b, chunk);
}

extern "C" void kernel_launch(void* const* d_in, const int* in_sizes, int n_in,
                              void* d_out, int out_size) {
    const float* boxes   = (const float*)d_in[0];   // [8,65536,4]
    const float* classes = (const float*)d_in[1];   // [8,65536,2]
    const float* anchors = (const float*)d_in[2];   // [65536,4]
    const float* gt      = (const float*)d_in[3];   // [8,32,4]
    const int*   nobj    = (const int*)d_in[4];     // [8]
    float* out = (float*)d_out;

    kFused<<<NBLK, 256>>>(boxes, classes, anchors, gt, nobj, out);
}